// round 8
// baseline (speedup 1.0000x reference)
#include <cuda_runtime.h>
#include <cuda_bf16.h>
#include <stdint.h>

// NT-Xent loss: symmetric block-triangle GEMM with persistent-strip CTAs.
// sim' = (z.z^T/0.5)*log2e via pre-scaled bf16 z. Upper triangle of the
// 128x128 block grid; tile (I,J) adds exp2(sim'-150) row-sums to block I and
// col-sums to block J. Each CTA owns (I, up to 16 consecutive J): A loaded
// once per chunk, J streamed through a 2-slot cp.async ring (J_{t+2}
// prefetched during epilogue/next GEMM). exp2 = zero-mean Schraudolph.

#define NTOT   16384
#define BROWS  8192
#define NCHUNK 576           // sum_I ceil((128-I)/16)
#define CHUNK  16
#define M0F    150.0f

__device__ __align__(128) unsigned char g_Zb[(size_t)NTOT * 256];   // 4 MB bf16
__device__ float  g_lrow[NTOT];
__device__ double g_acc;
__device__ double g_pos;

__device__ __forceinline__ uint32_t smem_u32(const void* p) {
    uint32_t a;
    asm("{ .reg .u64 t; cvta.to.shared.u64 t, %1; cvt.u32.u64 %0, t; }"
        : "=r"(a) : "l"(p));
    return a;
}

// Zero-mean Schraudolph 2^(x-150): bits = rn(x*2^23 + (127-c-150)*2^23),
// c = 0.05751 (E[ratio]=1 over uniform frac). Negative bits -> +0.
__device__ __forceinline__ float sexp(float x) {
    int b = __float2int_rn(fmaf(x, 8388608.f, -193420413.f));
    return __int_as_float(max(b, 0));
}

// -------------------------------------------------------------------- prep
__global__ void ntxent_prep(const float* __restrict__ zi,
                            const float* __restrict__ zj) {
    int idx = blockIdx.x * blockDim.x + threadIdx.x;
    if (idx < NTOT * 64) {
        int R = idx >> 6, c2 = idx & 63;
        float2 zv = (R < BROWS)
            ? ((const float2*)zi)[(size_t)R * 64 + c2]
            : ((const float2*)zj)[(size_t)(R - BROWS) * 64 + c2];
        const float a = 1.6986436f;    // sqrt(2*log2(e))
        __nv_bfloat162 h = __floats2bfloat162_rn(zv.x * a, zv.y * a);
        uint32_t bits = *reinterpret_cast<uint32_t*>(&h);
        int blk = R >> 7, rl = R & 127;
        int c = c2 * 2, chunk = c >> 3;
        uint32_t byte = (uint32_t)blk * 32768u + (uint32_t)rl * 256u
                      + (uint32_t)(((chunk ^ (rl & 7)) << 4) + (c & 7) * 2);
        *(uint32_t*)(g_Zb + byte) = bits;
    }
    if (idx < NTOT) g_lrow[idx] = 0.f;
    if (idx == 0) { g_acc = 0.0; g_pos = 0.0; }
}

// -------------------------------------------------------------------- main
__global__ void __launch_bounds__(256, 2) ntxent_main() {
    extern __shared__ unsigned char smem[];
    const int tid = threadIdx.x, lane = tid & 31, w = tid >> 5;
    const uint32_t sA = smem_u32(smem);          // A block, chunk-resident
    const uint32_t sR = sA + 32768;              // J ring: 2 x 32KB
    float* colsum = (float*)(smem + 98304);      // 128 floats

    // ---- chunk -> (I, Jstart, nJ); big chunks (small I) launch first ----
    int cidx = blockIdx.x;
    int I = 0, cb = 0;
    #pragma unroll 1
    for (;;) {
        int nch = (128 - I + CHUNK - 1) >> 4;
        if (cb + nch > cidx) break;
        cb += nch; I++;
    }
    const int Jstart = I + (cidx - cb) * CHUNK;
    const int nJ = min(CHUNK, 128 - Jstart);

    // ---- initial loads: G0 = {A, J0}, G1 = {J1 (maybe empty)} ----
    #pragma unroll
    for (int i = 0; i < 8; i++)
        asm volatile("cp.async.cg.shared.global [%0], [%1], 16;"
                     :: "r"(sA + tid * 16 + i * 4096),
                        "l"(g_Zb + (size_t)I * 32768 + tid * 16 + i * 4096));
    #pragma unroll
    for (int i = 0; i < 8; i++)
        asm volatile("cp.async.cg.shared.global [%0], [%1], 16;"
                     :: "r"(sR + tid * 16 + i * 4096),
                        "l"(g_Zb + (size_t)Jstart * 32768 + tid * 16 + i * 4096));
    asm volatile("cp.async.commit_group;");
    if (nJ > 1) {
        #pragma unroll
        for (int i = 0; i < 8; i++)
            asm volatile("cp.async.cg.shared.global [%0], [%1], 16;"
                         :: "r"(sR + 32768 + tid * 16 + i * 4096),
                            "l"(g_Zb + (size_t)(Jstart + 1) * 32768 + tid * 16 + i * 4096));
    }
    asm volatile("cp.async.commit_group;");
    if (tid < 128) colsum[tid] = 0.f;

    const int rBn = lane & 7, cBk = (lane >> 3) & 1, ntSel = lane >> 4;
    const int rowA = w * 16 + (lane & 15), cbA = lane >> 4;
    const int lr = w * 16 + (lane >> 2);         // accumulator rows lr, lr+8

    float rs0 = 0.f, rs1 = 0.f;                  // chunk-wide row sums

    #pragma unroll 1
    for (int t = 0; t < nJ; t++) {
        asm volatile("cp.async.wait_group 1;");  // J_t landed; J_{t+1} pending
        __syncthreads();
        const uint32_t sJ = sR + (t & 1) * 32768;
        const int J = Jstart + t;

        // ---- GEMM: C[16 n-tiles][4] (A via ldmatrix from resident sA) ----
        float c[16][4];
        #pragma unroll
        for (int nt = 0; nt < 16; nt++)
            c[nt][0] = c[nt][1] = c[nt][2] = c[nt][3] = 0.f;

        #pragma unroll
        for (int kc = 0; kc < 8; kc++) {
            uint32_t a0, a1, a2, a3;
            uint32_t addrA = sA + rowA * 256 + (((kc * 2 + cbA) ^ (rowA & 7)) << 4);
            asm volatile("ldmatrix.sync.aligned.m8n8.x4.shared.b16 {%0,%1,%2,%3}, [%4];"
                         : "=r"(a0), "=r"(a1), "=r"(a2), "=r"(a3) : "r"(addrA));
            #pragma unroll
            for (int np = 0; np < 8; np++) {
                int row = (np * 2 + ntSel) * 8 + rBn;
                uint32_t addrB = sJ + row * 256 + (((kc * 2 + cBk) ^ (row & 7)) << 4);
                uint32_t b0, b1, b2, b3;
                asm volatile("ldmatrix.sync.aligned.m8n8.x4.shared.b16 {%0,%1,%2,%3}, [%4];"
                             : "=r"(b0), "=r"(b1), "=r"(b2), "=r"(b3) : "r"(addrB));
                asm volatile("mma.sync.aligned.m16n8k16.row.col.f32.bf16.bf16.f32 "
                             "{%0,%1,%2,%3}, {%4,%5,%6,%7}, {%8,%9}, {%0,%1,%2,%3};"
                             : "+f"(c[np*2][0]), "+f"(c[np*2][1]),
                               "+f"(c[np*2][2]), "+f"(c[np*2][3])
                             : "r"(a0), "r"(a1), "r"(a2), "r"(a3), "r"(b0), "r"(b1));
                asm volatile("mma.sync.aligned.m16n8k16.row.col.f32.bf16.bf16.f32 "
                             "{%0,%1,%2,%3}, {%4,%5,%6,%7}, {%8,%9}, {%0,%1,%2,%3};"
                             : "+f"(c[np*2+1][0]), "+f"(c[np*2+1][1]),
                               "+f"(c[np*2+1][2]), "+f"(c[np*2+1][3])
                             : "r"(a0), "r"(a1), "r"(a2), "r"(a3), "r"(b2), "r"(b3));
            }
        }
        __syncthreads();                          // slot (t&1) reads complete

        // ---- prefetch J_{t+2} into the slot just freed ----
        if (t + 2 < nJ) {
            uint32_t sN = sR + (t & 1) * 32768;
            #pragma unroll
            for (int i = 0; i < 8; i++)
                asm volatile("cp.async.cg.shared.global [%0], [%1], 16;"
                             :: "r"(sN + tid * 16 + i * 4096),
                                "l"(g_Zb + (size_t)(Jstart + t + 2) * 32768 + tid * 16 + i * 4096));
        }
        asm volatile("cp.async.commit_group;");   // one group per tile, always

        // ---- positive pairs: J == I+64 tile holds sim[r, r^8192] on its
        //      local diagonal; each entry serves two symmetric rows -> 2x.
        if (J == I + 64) {
            int nt = lr >> 3, lc = lr & 7;
            float pv = 0.f;
            if ((lc >> 1) == (lane & 3)) {
                pv  = c[nt][lc & 1];
                pv += c[(lr + 8) >> 3][2 + (lc & 1)];
            }
            #pragma unroll
            for (int o = 16; o >= 1; o >>= 1)
                pv += __shfl_xor_sync(0xffffffffu, pv, o);
            if (lane == 0) atomicAdd(&g_pos, 2.0 * (double)pv);
        }
        // ---- diagonal mask on I==J (sentinel underflows in sexp) ----
        if (I == J) {
            int nt = lr >> 3, lc = lr & 7;
            if ((lc >> 1) == (lane & 3)) {
                c[nt][lc & 1] = -1e30f;
                c[(lr + 8) >> 3][2 + (lc & 1)] = -1e30f;
            }
        }

        // ---- epilogue: exp2(x-150); rows to regs, cols to smem ----
        const bool doCols = (I != J);
        #pragma unroll
        for (int nt = 0; nt < 16; nt++) {
            float e0 = sexp(c[nt][0]);
            float e1 = sexp(c[nt][1]);
            float e2 = sexp(c[nt][2]);
            float e3 = sexp(c[nt][3]);
            rs0 += e0 + e1;
            rs1 += e2 + e3;
            if (doCols) {
                float ca = e0 + e2, cb2 = e1 + e3;  // cols nt*8+(lane&3)*2, +1
                #pragma unroll
                for (int o = 4; o <= 16; o <<= 1) {
                    ca  += __shfl_xor_sync(0xffffffffu, ca, o);
                    cb2 += __shfl_xor_sync(0xffffffffu, cb2, o);
                }
                if (lane < 4) {
                    atomicAdd(&colsum[nt * 8 + lane * 2], ca);
                    atomicAdd(&colsum[nt * 8 + lane * 2 + 1], cb2);
                }
            }
        }
        __syncthreads();                          // colsum writes complete
        if (tid < 128) {
            if (doCols) atomicAdd(&g_lrow[J * 128 + tid], colsum[tid]);
            colsum[tid] = 0.f;                    // reset for next tile
        }
    }

    // ---- flush chunk-wide row sums ----
    #pragma unroll
    for (int o = 1; o <= 2; o <<= 1) {
        rs0 += __shfl_xor_sync(0xffffffffu, rs0, o);
        rs1 += __shfl_xor_sync(0xffffffffu, rs1, o);
    }
    if ((lane & 3) == 0) {
        atomicAdd(&g_lrow[I * 128 + lr], rs0);
        atomicAdd(&g_lrow[I * 128 + lr + 8], rs1);
    }
}

// -------------------------------------------------------------------- fin
__global__ void ntxent_fin1() {
    int r = blockIdx.x * 256 + threadIdx.x;
    float v = M0F + log2f(g_lrow[r]);
    #pragma unroll
    for (int o = 16; o >= 1; o >>= 1)
        v += __shfl_xor_sync(0xffffffffu, v, o);
    if ((threadIdx.x & 31) == 0) atomicAdd(&g_acc, (double)v);
}

__global__ void ntxent_fin2(float* out) {
    out[0] = (float)((g_acc - g_pos) * 0.6931471805599453 / (double)NTOT);
}

// ---------------------------------------------------------------------------
extern "C" void kernel_launch(void* const* d_in, const int* in_sizes, int n_in,
                              void* d_out, int out_size) {
    const float* zi = (const float*)d_in[0];
    const float* zj = (const float*)d_in[1];
    float* out = (float*)d_out;

    cudaFuncSetAttribute(ntxent_main,
                         cudaFuncAttributeMaxDynamicSharedMemorySize, 98816);

    ntxent_prep<<<(NTOT * 64) / 256, 256>>>(zi, zj);
    ntxent_main<<<NCHUNK, 256, 98816>>>();
    ntxent_fin1<<<NTOT / 256, 256>>>();
    ntxent_fin2<<<1, 1>>>(out);
}

// round 9
// speedup vs baseline: 1.1406x; 1.1406x over previous
#include <cuda_runtime.h>
#include <cuda_bf16.h>
#include <stdint.h>
#include <math.h>

// NT-Xent loss, symmetric-GEMM version (round-6 structure + Schraudolph exp).
// sim' = (z.z^T/0.5)*log2e via pre-scaled bf16 z. Upper triangle of the
// 128x128 block grid (8256 pair-tiles, one per CTA): tile (I,J) adds
// exp2(sim'-150) row-sums to block I and col-sums to block J. Fixed shift
// makes accumulation order-free. exp2 = zero-mean Schraudolph (3 instrs).

#define NTOT   16384
#define BROWS  8192
#define NPAIR  8256          // 128*129/2 pair-tiles
#define M0F    150.0f

__device__ __align__(128) unsigned char g_Zb[(size_t)NTOT * 256];   // 4 MB bf16
__device__ float  g_lrow[NTOT];
__device__ double g_acc;     // sum of lse (log2 units)
__device__ double g_pos;     // sum of positive-pair sims (log2 units)

__device__ __forceinline__ uint32_t smem_u32(const void* p) {
    uint32_t a;
    asm("{ .reg .u64 t; cvta.to.shared.u64 t, %1; cvt.u32.u64 %0, t; }"
        : "=r"(a) : "l"(p));
    return a;
}

// Zero-mean Schraudolph 2^(x-150): bits = rn(x*2^23 + (127-c-150)*2^23),
// c = 0.05751 (E[ratio]=1 over uniform frac). Negative bits -> +0.
__device__ __forceinline__ float sexp(float x) {
    int b = __float2int_rn(fmaf(x, 8388608.f, -193420413.f));
    return __int_as_float(max(b, 0));
}

// -------------------------------------------------------------------- prep
// Gather+scale z to bf16 in per-128-row-block layout (32KB/block):
// byte = blk*32768 + rl*256 + ((chunk ^ (rl&7))<<4) + (col&7)*2, chunk=col>>3
__global__ void ntxent_prep(const float* __restrict__ zi,
                            const float* __restrict__ zj) {
    int idx = blockIdx.x * blockDim.x + threadIdx.x;
    if (idx < NTOT * 64) {
        int R = idx >> 6, c2 = idx & 63;
        float2 zv = (R < BROWS)
            ? ((const float2*)zi)[(size_t)R * 64 + c2]
            : ((const float2*)zj)[(size_t)(R - BROWS) * 64 + c2];
        const float a = 1.6986436f;    // sqrt(2*log2(e))
        __nv_bfloat162 h = __floats2bfloat162_rn(zv.x * a, zv.y * a);
        uint32_t bits = *reinterpret_cast<uint32_t*>(&h);
        int blk = R >> 7, rl = R & 127;
        int c = c2 * 2, chunk = c >> 3;
        uint32_t byte = (uint32_t)blk * 32768u + (uint32_t)rl * 256u
                      + (uint32_t)(((chunk ^ (rl & 7)) << 4) + (c & 7) * 2);
        *(uint32_t*)(g_Zb + byte) = bits;
    }
    if (idx < NTOT) g_lrow[idx] = 0.f;
    if (idx == 0) { g_acc = 0.0; g_pos = 0.0; }
}

// -------------------------------------------------------------------- main
// One pair-tile per CTA. 256 threads = 8 warps; warp w computes rows
// w*16..w*16+15 of block I against all 128 cols of block J.
__global__ void __launch_bounds__(256, 2) ntxent_main() {
    extern __shared__ unsigned char smem[];
    const int tid = threadIdx.x, lane = tid & 31, w = tid >> 5;
    const uint32_t sI = smem_u32(smem);          // [0, 32768)
    const uint32_t sJ = sI + 32768;              // [32768, 65536)
    float* colsum = (float*)(smem + 65536);      // [65536, 66048)

    // triangle index -> (I, J), I <= J
    const int b = blockIdx.x;
    const int I = (int)(128.5 - sqrt(128.5 * 128.5 - 2.0 * (double)b));
    const int J = I + (b - (I * 128 - (I * (I - 1)) / 2));

    // ---- load both 32KB blocks ----
    #pragma unroll
    for (int i = 0; i < 8; i++)
        asm volatile("cp.async.cg.shared.global [%0], [%1], 16;"
                     :: "r"(sI + tid * 16 + i * 4096),
                        "l"(g_Zb + (size_t)I * 32768 + tid * 16 + i * 4096));
    #pragma unroll
    for (int i = 0; i < 8; i++)
        asm volatile("cp.async.cg.shared.global [%0], [%1], 16;"
                     :: "r"(sJ + tid * 16 + i * 4096),
                        "l"(g_Zb + (size_t)J * 32768 + tid * 16 + i * 4096));
    asm volatile("cp.async.commit_group;");
    if (tid < 128) colsum[tid] = 0.f;
    asm volatile("cp.async.wait_group 0;");
    __syncthreads();

    // ---- GEMM: C[16 n-tiles][4] ----
    float c[16][4];
    #pragma unroll
    for (int nt = 0; nt < 16; nt++)
        c[nt][0] = c[nt][1] = c[nt][2] = c[nt][3] = 0.f;

    const int rBn = lane & 7, cBk = (lane >> 3) & 1, ntSel = lane >> 4;
    const int rowA = w * 16 + (lane & 15), cbA = lane >> 4;

    #pragma unroll
    for (int kc = 0; kc < 8; kc++) {
        uint32_t a0, a1, a2, a3;
        uint32_t addrA = sI + rowA * 256 + (((kc * 2 + cbA) ^ (rowA & 7)) << 4);
        asm volatile("ldmatrix.sync.aligned.m8n8.x4.shared.b16 {%0,%1,%2,%3}, [%4];"
                     : "=r"(a0), "=r"(a1), "=r"(a2), "=r"(a3) : "r"(addrA));
        #pragma unroll
        for (int np = 0; np < 8; np++) {
            int row = (np * 2 + ntSel) * 8 + rBn;
            uint32_t addrB = sJ + row * 256 + (((kc * 2 + cBk) ^ (row & 7)) << 4);
            uint32_t b0, b1, b2, b3;
            asm volatile("ldmatrix.sync.aligned.m8n8.x4.shared.b16 {%0,%1,%2,%3}, [%4];"
                         : "=r"(b0), "=r"(b1), "=r"(b2), "=r"(b3) : "r"(addrB));
            asm volatile("mma.sync.aligned.m16n8k16.row.col.f32.bf16.bf16.f32 "
                         "{%0,%1,%2,%3}, {%4,%5,%6,%7}, {%8,%9}, {%0,%1,%2,%3};"
                         : "+f"(c[np*2][0]), "+f"(c[np*2][1]),
                           "+f"(c[np*2][2]), "+f"(c[np*2][3])
                         : "r"(a0), "r"(a1), "r"(a2), "r"(a3), "r"(b0), "r"(b1));
            asm volatile("mma.sync.aligned.m16n8k16.row.col.f32.bf16.bf16.f32 "
                         "{%0,%1,%2,%3}, {%4,%5,%6,%7}, {%8,%9}, {%0,%1,%2,%3};"
                         : "+f"(c[np*2+1][0]), "+f"(c[np*2+1][1]),
                           "+f"(c[np*2+1][2]), "+f"(c[np*2+1][3])
                         : "r"(a0), "r"(a1), "r"(a2), "r"(a3), "r"(b2), "r"(b3));
        }
    }

    // local row of this thread's accumulator rows: lr (and lr+8)
    const int lr = w * 16 + (lane >> 2);

    // ---- positive-pair capture: tiles with J == I+64 hold sim[r, r^8192]
    // on their local diagonal; each entry serves TWO rows (symmetry) -> 2x.
    if (J == I + 64 && I < 64) {
        int nt = lr >> 3, lc = lr & 7;
        float pv = 0.f;
        if ((lc >> 1) == (lane & 3)) {
            pv  = c[nt][lc & 1];
            pv += c[(lr + 8) >> 3][2 + (lc & 1)];
        }
        #pragma unroll
        for (int o = 16; o >= 1; o >>= 1)
            pv += __shfl_xor_sync(0xffffffffu, pv, o);
        if (lane == 0) atomicAdd(&g_pos, 2.0 * (double)pv);
    }
    // ---- diagonal mask on I==J tiles (sentinel underflows in sexp) ----
    if (I == J) {
        int nt = lr >> 3, lc = lr & 7;
        if ((lc >> 1) == (lane & 3)) {
            c[nt][lc & 1] = -1e30f;
            c[(lr + 8) >> 3][2 + (lc & 1)] = -1e30f;
        }
    }

    // ---- epilogue: Schraudolph exp2(x-150); row + column partials ----
    float rs0 = 0.f, rs1 = 0.f;
    const bool doCols = (I != J);
    #pragma unroll
    for (int nt = 0; nt < 16; nt++) {
        float e0 = sexp(c[nt][0]);
        float e1 = sexp(c[nt][1]);
        float e2 = sexp(c[nt][2]);
        float e3 = sexp(c[nt][3]);
        rs0 += e0 + e1;
        rs1 += e2 + e3;
        if (doCols) {
            float ca = e0 + e2, cb = e1 + e3;      // cols nt*8+(lane&3)*2, +1
            #pragma unroll
            for (int o = 4; o <= 16; o <<= 1) {
                ca += __shfl_xor_sync(0xffffffffu, ca, o);
                cb += __shfl_xor_sync(0xffffffffu, cb, o);
            }
            if (lane < 4) {
                atomicAdd(&colsum[nt * 8 + lane * 2], ca);
                atomicAdd(&colsum[nt * 8 + lane * 2 + 1], cb);
            }
        }
    }
    // reduce rows across the 4 lanes sharing them, flush to global
    #pragma unroll
    for (int o = 1; o <= 2; o <<= 1) {
        rs0 += __shfl_xor_sync(0xffffffffu, rs0, o);
        rs1 += __shfl_xor_sync(0xffffffffu, rs1, o);
    }
    if ((lane & 3) == 0) {
        atomicAdd(&g_lrow[I * 128 + lr], rs0);
        atomicAdd(&g_lrow[I * 128 + lr + 8], rs1);
    }

    __syncthreads();
    if (doCols && tid < 128)
        atomicAdd(&g_lrow[J * 128 + tid], colsum[tid]);
}

// -------------------------------------------------------------------- fin
__global__ void ntxent_fin1() {
    int r = blockIdx.x * 256 + threadIdx.x;
    float v = M0F + log2f(g_lrow[r]);
    #pragma unroll
    for (int o = 16; o >= 1; o >>= 1)
        v += __shfl_xor_sync(0xffffffffu, v, o);
    if ((threadIdx.x & 31) == 0) atomicAdd(&g_acc, (double)v);
}

__global__ void ntxent_fin2(float* out) {
    out[0] = (float)((g_acc - g_pos) * 0.6931471805599453 / (double)NTOT);
}

// ---------------------------------------------------------------------------
extern "C" void kernel_launch(void* const* d_in, const int* in_sizes, int n_in,
                              void* d_out, int out_size) {
    const float* zi = (const float*)d_in[0];
    const float* zj = (const float*)d_in[1];
    float* out = (float*)d_out;

    cudaFuncSetAttribute(ntxent_main,
                         cudaFuncAttributeMaxDynamicSharedMemorySize, 66048);

    ntxent_prep<<<(NTOT * 64) / 256, 256>>>(zi, zj);
    ntxent_main<<<NPAIR, 256, 66048>>>();
    ntxent_fin1<<<NTOT / 256, 256>>>();
    ntxent_fin2<<<1, 1>>>(out);
}

// round 10
// speedup vs baseline: 1.5405x; 1.3506x over previous
#include <cuda_runtime.h>
#include <cuda_bf16.h>
#include <stdint.h>
#include <math.h>

// NT-Xent loss, symmetric-GEMM, 2D warp tiling (4x2).
// sim' = (z.z^T/0.5)*log2e via pre-scaled bf16 z. Upper triangle of the
// 128x128 block grid (8256 pair-tiles, one per CTA): tile (I,J) adds
// exp2(sim'-150) row-sums to block I and col-sums to block J (order-free).
// Warp (mw=w>>1, ch=w&1) computes rows mw*32..+32 x cols ch*64..+64:
// each B fragment feeds 2 MMAs -> 33% less smem read traffic than 1D tiling.

#define NTOT   16384
#define BROWS  8192
#define NPAIR  8256
#define M0F    150.0f

__device__ __align__(128) unsigned char g_Zb[(size_t)NTOT * 256];   // 4 MB bf16
__device__ float  g_lrow[NTOT];
__device__ double g_acc;
__device__ double g_pos;

__device__ __forceinline__ uint32_t smem_u32(const void* p) {
    uint32_t a;
    asm("{ .reg .u64 t; cvta.to.shared.u64 t, %1; cvt.u32.u64 %0, t; }"
        : "=r"(a) : "l"(p));
    return a;
}

// Zero-mean Schraudolph 2^(x-150). Negative bits -> +0 (handles -1e30 mask).
__device__ __forceinline__ float sexp(float x) {
    int b = __float2int_rn(fmaf(x, 8388608.f, -193420413.f));
    return __int_as_float(max(b, 0));
}

// -------------------------------------------------------------------- prep
__global__ void ntxent_prep(const float* __restrict__ zi,
                            const float* __restrict__ zj) {
    int idx = blockIdx.x * blockDim.x + threadIdx.x;
    if (idx < NTOT * 64) {
        int R = idx >> 6, c2 = idx & 63;
        float2 zv = (R < BROWS)
            ? ((const float2*)zi)[(size_t)R * 64 + c2]
            : ((const float2*)zj)[(size_t)(R - BROWS) * 64 + c2];
        const float a = 1.6986436f;    // sqrt(2*log2(e))
        __nv_bfloat162 h = __floats2bfloat162_rn(zv.x * a, zv.y * a);
        uint32_t bits = *reinterpret_cast<uint32_t*>(&h);
        int blk = R >> 7, rl = R & 127;
        int c = c2 * 2, chunk = c >> 3;
        uint32_t byte = (uint32_t)blk * 32768u + (uint32_t)rl * 256u
                      + (uint32_t)(((chunk ^ (rl & 7)) << 4) + (c & 7) * 2);
        *(uint32_t*)(g_Zb + byte) = bits;
    }
    if (idx < NTOT) g_lrow[idx] = 0.f;
    if (idx == 0) { g_acc = 0.0; g_pos = 0.0; }
}

// -------------------------------------------------------------------- main
__global__ void __launch_bounds__(256, 2) ntxent_main() {
    extern __shared__ unsigned char smem[];
    const int tid = threadIdx.x, lane = tid & 31, w = tid >> 5;
    const int mw = w >> 1, ch = w & 1;           // 4x2 warp grid
    const uint32_t sI = smem_u32(smem);          // [0, 32768)
    const uint32_t sJ = sI + 32768;              // [32768, 65536)
    float* colsum = (float*)(smem + 65536);      // 128 floats

    const int b = blockIdx.x;
    const int I = (int)(128.5 - sqrt(128.5 * 128.5 - 2.0 * (double)b));
    const int J = I + (b - (I * 128 - (I * (I - 1)) / 2));

    // ---- load both 32KB blocks ----
    #pragma unroll
    for (int i = 0; i < 8; i++)
        asm volatile("cp.async.cg.shared.global [%0], [%1], 16;"
                     :: "r"(sI + tid * 16 + i * 4096),
                        "l"(g_Zb + (size_t)I * 32768 + tid * 16 + i * 4096));
    #pragma unroll
    for (int i = 0; i < 8; i++)
        asm volatile("cp.async.cg.shared.global [%0], [%1], 16;"
                     :: "r"(sJ + tid * 16 + i * 4096),
                        "l"(g_Zb + (size_t)J * 32768 + tid * 16 + i * 4096));
    asm volatile("cp.async.commit_group;");
    if (tid < 128) colsum[tid] = 0.f;
    asm volatile("cp.async.wait_group 0;");
    __syncthreads();

    // ---- GEMM: c[mt 0..1][nt 0..7][4] ----
    float c[2][8][4];
    #pragma unroll
    for (int mt = 0; mt < 2; mt++)
        #pragma unroll
        for (int nt = 0; nt < 8; nt++)
            c[mt][nt][0] = c[mt][nt][1] = c[mt][nt][2] = c[mt][nt][3] = 0.f;

    const int rBn = lane & 7, cBk = (lane >> 3) & 1, ntSel = lane >> 4;
    const int rowA0 = mw * 32 + (lane & 15), cbA = lane >> 4;
    const int rowA1 = rowA0 + 16;

    #pragma unroll
    for (int kc = 0; kc < 8; kc++) {
        uint32_t a00, a01, a02, a03, a10, a11, a12, a13;
        uint32_t adrA0 = sI + rowA0 * 256 + (((kc * 2 + cbA) ^ (rowA0 & 7)) << 4);
        uint32_t adrA1 = sI + rowA1 * 256 + (((kc * 2 + cbA) ^ (rowA1 & 7)) << 4);
        asm volatile("ldmatrix.sync.aligned.m8n8.x4.shared.b16 {%0,%1,%2,%3}, [%4];"
                     : "=r"(a00), "=r"(a01), "=r"(a02), "=r"(a03) : "r"(adrA0));
        asm volatile("ldmatrix.sync.aligned.m8n8.x4.shared.b16 {%0,%1,%2,%3}, [%4];"
                     : "=r"(a10), "=r"(a11), "=r"(a12), "=r"(a13) : "r"(adrA1));
        #pragma unroll
        for (int np = 0; np < 4; np++) {
            int row = ch * 64 + (np * 2 + ntSel) * 8 + rBn;
            uint32_t adrB = sJ + row * 256 + (((kc * 2 + cBk) ^ (row & 7)) << 4);
            uint32_t b0, b1, b2, b3;
            asm volatile("ldmatrix.sync.aligned.m8n8.x4.shared.b16 {%0,%1,%2,%3}, [%4];"
                         : "=r"(b0), "=r"(b1), "=r"(b2), "=r"(b3) : "r"(adrB));
            asm volatile("mma.sync.aligned.m16n8k16.row.col.f32.bf16.bf16.f32 "
                         "{%0,%1,%2,%3}, {%4,%5,%6,%7}, {%8,%9}, {%0,%1,%2,%3};"
                         : "+f"(c[0][np*2][0]), "+f"(c[0][np*2][1]),
                           "+f"(c[0][np*2][2]), "+f"(c[0][np*2][3])
                         : "r"(a00), "r"(a01), "r"(a02), "r"(a03), "r"(b0), "r"(b1));
            asm volatile("mma.sync.aligned.m16n8k16.row.col.f32.bf16.bf16.f32 "
                         "{%0,%1,%2,%3}, {%4,%5,%6,%7}, {%8,%9}, {%0,%1,%2,%3};"
                         : "+f"(c[0][np*2+1][0]), "+f"(c[0][np*2+1][1]),
                           "+f"(c[0][np*2+1][2]), "+f"(c[0][np*2+1][3])
                         : "r"(a00), "r"(a01), "r"(a02), "r"(a03), "r"(b2), "r"(b3));
            asm volatile("mma.sync.aligned.m16n8k16.row.col.f32.bf16.bf16.f32 "
                         "{%0,%1,%2,%3}, {%4,%5,%6,%7}, {%8,%9}, {%0,%1,%2,%3};"
                         : "+f"(c[1][np*2][0]), "+f"(c[1][np*2][1]),
                           "+f"(c[1][np*2][2]), "+f"(c[1][np*2][3])
                         : "r"(a10), "r"(a11), "r"(a12), "r"(a13), "r"(b0), "r"(b1));
            asm volatile("mma.sync.aligned.m16n8k16.row.col.f32.bf16.bf16.f32 "
                         "{%0,%1,%2,%3}, {%4,%5,%6,%7}, {%8,%9}, {%0,%1,%2,%3};"
                         : "+f"(c[1][np*2+1][0]), "+f"(c[1][np*2+1][1]),
                           "+f"(c[1][np*2+1][2]), "+f"(c[1][np*2+1][3])
                         : "r"(a10), "r"(a11), "r"(a12), "r"(a13), "r"(b2), "r"(b3));
        }
    }

    const int q = lane >> 2;   // thread's row pair within an m-tile: q, q+8

    // ---- positive pairs (tile J == I+64; diag element (lr,lr) lives in the
    //      warp with mw = lr>>5, which always satisfies mw>>1 == ch) ----
    if (J == I + 64 && (mw >> 1) == ch) {
        float pv = 0.f;
        if ((lane & 3) == (q >> 1)) {
            int j = q & 1;
            #pragma unroll
            for (int mt = 0; mt < 2; mt++) {
                int ntp = (mw & 1) * 4 + mt * 2;
                pv += c[mt][ntp][j];             // row lo, col = row
                pv += c[mt][ntp + 1][2 + j];     // row hi, col = row
            }
        }
        #pragma unroll
        for (int o = 16; o >= 1; o >>= 1)
            pv += __shfl_xor_sync(0xffffffffu, pv, o);
        if (lane == 0) atomicAdd(&g_pos, 2.0 * (double)pv);
    }
    // ---- diagonal mask on I==J tiles ----
    if (I == J && (mw >> 1) == ch) {
        if ((lane & 3) == (q >> 1)) {
            int j = q & 1;
            #pragma unroll
            for (int mt = 0; mt < 2; mt++) {
                int ntp = (mw & 1) * 4 + mt * 2;
                c[mt][ntp][j] = -1e30f;
                c[mt][ntp + 1][2 + j] = -1e30f;
            }
        }
    }

    // ---- epilogue: exp2(x-150); row sums (regs) + col sums (smem) ----
    const bool doCols = (I != J);
    float rl[2] = {0.f, 0.f}, rh[2] = {0.f, 0.f};
    #pragma unroll
    for (int nt = 0; nt < 8; nt++) {
        float e00 = sexp(c[0][nt][0]), e01 = sexp(c[0][nt][1]);
        float e02 = sexp(c[0][nt][2]), e03 = sexp(c[0][nt][3]);
        float e10 = sexp(c[1][nt][0]), e11 = sexp(c[1][nt][1]);
        float e12 = sexp(c[1][nt][2]), e13 = sexp(c[1][nt][3]);
        rl[0] += e00 + e01;  rh[0] += e02 + e03;
        rl[1] += e10 + e11;  rh[1] += e12 + e13;
        if (doCols) {
            float ca = (e00 + e02) + (e10 + e12);   // col nt*8+(lane&3)*2
            float cb = (e01 + e03) + (e11 + e13);   // col +1
            #pragma unroll
            for (int o = 4; o <= 16; o <<= 1) {
                ca += __shfl_xor_sync(0xffffffffu, ca, o);
                cb += __shfl_xor_sync(0xffffffffu, cb, o);
            }
            if (lane < 4) {
                atomicAdd(&colsum[ch * 64 + nt * 8 + lane * 2], ca);
                atomicAdd(&colsum[ch * 64 + nt * 8 + lane * 2 + 1], cb);
            }
        }
    }
    // reduce rows across the 4 lanes sharing q, flush to global
    #pragma unroll
    for (int o = 1; o <= 2; o <<= 1) {
        rl[0] += __shfl_xor_sync(0xffffffffu, rl[0], o);
        rh[0] += __shfl_xor_sync(0xffffffffu, rh[0], o);
        rl[1] += __shfl_xor_sync(0xffffffffu, rl[1], o);
        rh[1] += __shfl_xor_sync(0xffffffffu, rh[1], o);
    }
    if ((lane & 3) == 0) {
        #pragma unroll
        for (int mt = 0; mt < 2; mt++) {
            int r = I * 128 + mw * 32 + mt * 16 + q;
            atomicAdd(&g_lrow[r], rl[mt]);
            atomicAdd(&g_lrow[r + 8], rh[mt]);
        }
    }

    __syncthreads();
    if (doCols && tid < 128)
        atomicAdd(&g_lrow[J * 128 + tid], colsum[tid]);
}

// -------------------------------------------------------------------- fin
__global__ void ntxent_fin1() {
    int r = blockIdx.x * 256 + threadIdx.x;
    float v = M0F + log2f(g_lrow[r]);
    #pragma unroll
    for (int o = 16; o >= 1; o >>= 1)
        v += __shfl_xor_sync(0xffffffffu, v, o);
    if ((threadIdx.x & 31) == 0) atomicAdd(&g_acc, (double)v);
}

__global__ void ntxent_fin2(float* out) {
    out[0] = (float)((g_acc - g_pos) * 0.6931471805599453 / (double)NTOT);
}

// ---------------------------------------------------------------------------
extern "C" void kernel_launch(void* const* d_in, const int* in_sizes, int n_in,
                              void* d_out, int out_size) {
    const float* zi = (const float*)d_in[0];
    const float* zj = (const float*)d_in[1];
    float* out = (float*)d_out;

    cudaFuncSetAttribute(ntxent_main,
                         cudaFuncAttributeMaxDynamicSharedMemorySize, 66048);

    ntxent_prep<<<(NTOT * 64) / 256, 256>>>(zi, zj);
    ntxent_main<<<NPAIR, 256, 66048>>>();
    ntxent_fin1<<<NTOT / 256, 256>>>();
    ntxent_fin2<<<1, 1>>>(out);
}

// round 11
// speedup vs baseline: 2.5621x; 1.6632x over previous
#include <cuda_runtime.h>
#include <cuda_fp16.h>
#include <stdint.h>
#include <math.h>

// NT-Xent loss, symmetric-GEMM, 2D warp tiling (4x2), fp16 MMA with fp16
// accumulators (2x tensor rate vs f32 accum). sim' = (z.z^T/0.5)*log2e via
// pre-scaled fp16 z. Upper triangle of the 128x128 block grid (8256 tiles,
// one per CTA): tile (I,J) adds exp2(sim'-150) row-sums to block I and
// col-sums to block J (order-free). exp2 = zero-mean Schraudolph.

#define NTOT   16384
#define BROWS  8192
#define NPAIR  8256
#define M0F    150.0f

__device__ __align__(128) unsigned char g_Zb[(size_t)NTOT * 256];   // 4 MB fp16
__device__ float  g_lrow[NTOT];
__device__ double g_acc;
__device__ double g_pos;

__device__ __forceinline__ uint32_t smem_u32(const void* p) {
    uint32_t a;
    asm("{ .reg .u64 t; cvta.to.shared.u64 t, %1; cvt.u32.u64 %0, t; }"
        : "=r"(a) : "l"(p));
    return a;
}

// Zero-mean Schraudolph 2^(x-150). Negative bits -> +0 (handles -1e30 mask).
__device__ __forceinline__ float sexp(float x) {
    int b = __float2int_rn(fmaf(x, 8388608.f, -193420413.f));
    return __int_as_float(max(b, 0));
}

__device__ __forceinline__ float2 h2f2(uint32_t h) {
    __half2 v = *reinterpret_cast<__half2*>(&h);
    return __half22float2(v);
}

// -------------------------------------------------------------------- prep
__global__ void ntxent_prep(const float* __restrict__ zi,
                            const float* __restrict__ zj) {
    int idx = blockIdx.x * blockDim.x + threadIdx.x;
    if (idx < NTOT * 64) {
        int R = idx >> 6, c2 = idx & 63;
        float2 zv = (R < BROWS)
            ? ((const float2*)zi)[(size_t)R * 64 + c2]
            : ((const float2*)zj)[(size_t)(R - BROWS) * 64 + c2];
        const float a = 1.6986436f;    // sqrt(2*log2(e))
        __half2 h = __floats2half2_rn(zv.x * a, zv.y * a);
        uint32_t bits = *reinterpret_cast<uint32_t*>(&h);
        int blk = R >> 7, rl = R & 127;
        int c = c2 * 2, chunk = c >> 3;
        uint32_t byte = (uint32_t)blk * 32768u + (uint32_t)rl * 256u
                      + (uint32_t)(((chunk ^ (rl & 7)) << 4) + (c & 7) * 2);
        *(uint32_t*)(g_Zb + byte) = bits;
    }
    if (idx < NTOT) g_lrow[idx] = 0.f;
    if (idx == 0) { g_acc = 0.0; g_pos = 0.0; }
}

// -------------------------------------------------------------------- main
__global__ void __launch_bounds__(256, 3) ntxent_main() {
    extern __shared__ unsigned char smem[];
    const int tid = threadIdx.x, lane = tid & 31, w = tid >> 5;
    const int mw = w >> 1, ch = w & 1;           // 4x2 warp grid
    const uint32_t sI = smem_u32(smem);          // [0, 32768)
    const uint32_t sJ = sI + 32768;              // [32768, 65536)
    float* colsum = (float*)(smem + 65536);      // 128 floats

    const int b = blockIdx.x;
    const int I = (int)(128.5 - sqrt(128.5 * 128.5 - 2.0 * (double)b));
    const int J = I + (b - (I * 128 - (I * (I - 1)) / 2));

    // ---- load both 32KB blocks ----
    #pragma unroll
    for (int i = 0; i < 8; i++)
        asm volatile("cp.async.cg.shared.global [%0], [%1], 16;"
                     :: "r"(sI + tid * 16 + i * 4096),
                        "l"(g_Zb + (size_t)I * 32768 + tid * 16 + i * 4096));
    #pragma unroll
    for (int i = 0; i < 8; i++)
        asm volatile("cp.async.cg.shared.global [%0], [%1], 16;"
                     :: "r"(sJ + tid * 16 + i * 4096),
                        "l"(g_Zb + (size_t)J * 32768 + tid * 16 + i * 4096));
    asm volatile("cp.async.commit_group;");
    if (tid < 128) colsum[tid] = 0.f;
    asm volatile("cp.async.wait_group 0;");
    __syncthreads();

    // ---- GEMM: f16x2 accumulators ch[mt 0..1][nt 0..7][2] ----
    uint32_t cacc[2][8][2];
    #pragma unroll
    for (int mt = 0; mt < 2; mt++)
        #pragma unroll
        for (int nt = 0; nt < 8; nt++)
            cacc[mt][nt][0] = cacc[mt][nt][1] = 0u;

    const int rBn = lane & 7, cBk = (lane >> 3) & 1, ntSel = lane >> 4;
    const int rowA0 = mw * 32 + (lane & 15), cbA = lane >> 4;
    const int rowA1 = rowA0 + 16;

    #pragma unroll
    for (int kc = 0; kc < 8; kc++) {
        uint32_t a00, a01, a02, a03, a10, a11, a12, a13;
        uint32_t adrA0 = sI + rowA0 * 256 + (((kc * 2 + cbA) ^ (rowA0 & 7)) << 4);
        uint32_t adrA1 = sI + rowA1 * 256 + (((kc * 2 + cbA) ^ (rowA1 & 7)) << 4);
        asm volatile("ldmatrix.sync.aligned.m8n8.x4.shared.b16 {%0,%1,%2,%3}, [%4];"
                     : "=r"(a00), "=r"(a01), "=r"(a02), "=r"(a03) : "r"(adrA0));
        asm volatile("ldmatrix.sync.aligned.m8n8.x4.shared.b16 {%0,%1,%2,%3}, [%4];"
                     : "=r"(a10), "=r"(a11), "=r"(a12), "=r"(a13) : "r"(adrA1));
        #pragma unroll
        for (int np = 0; np < 4; np++) {
            int row = ch * 64 + (np * 2 + ntSel) * 8 + rBn;
            uint32_t adrB = sJ + row * 256 + (((kc * 2 + cBk) ^ (row & 7)) << 4);
            uint32_t b0, b1, b2, b3;
            asm volatile("ldmatrix.sync.aligned.m8n8.x4.shared.b16 {%0,%1,%2,%3}, [%4];"
                         : "=r"(b0), "=r"(b1), "=r"(b2), "=r"(b3) : "r"(adrB));
            asm volatile("mma.sync.aligned.m16n8k16.row.col.f16.f16.f16.f16 "
                         "{%0,%1}, {%2,%3,%4,%5}, {%6,%7}, {%0,%1};"
                         : "+r"(cacc[0][np*2][0]), "+r"(cacc[0][np*2][1])
                         : "r"(a00), "r"(a01), "r"(a02), "r"(a03), "r"(b0), "r"(b1));
            asm volatile("mma.sync.aligned.m16n8k16.row.col.f16.f16.f16.f16 "
                         "{%0,%1}, {%2,%3,%4,%5}, {%6,%7}, {%0,%1};"
                         : "+r"(cacc[0][np*2+1][0]), "+r"(cacc[0][np*2+1][1])
                         : "r"(a00), "r"(a01), "r"(a02), "r"(a03), "r"(b2), "r"(b3));
            asm volatile("mma.sync.aligned.m16n8k16.row.col.f16.f16.f16.f16 "
                         "{%0,%1}, {%2,%3,%4,%5}, {%6,%7}, {%0,%1};"
                         : "+r"(cacc[1][np*2][0]), "+r"(cacc[1][np*2][1])
                         : "r"(a10), "r"(a11), "r"(a12), "r"(a13), "r"(b0), "r"(b1));
            asm volatile("mma.sync.aligned.m16n8k16.row.col.f16.f16.f16.f16 "
                         "{%0,%1}, {%2,%3,%4,%5}, {%6,%7}, {%0,%1};"
                         : "+r"(cacc[1][np*2+1][0]), "+r"(cacc[1][np*2+1][1])
                         : "r"(a10), "r"(a11), "r"(a12), "r"(a13), "r"(b2), "r"(b3));
        }
    }

    const int q = lane >> 2;              // row pair within m-tile: q, q+8
    const bool diagWarp = ((mw >> 1) == ch);
    const bool thOwn = ((lane & 3) == (q >> 1));
    const int jsel = q & 1;
    const int ntp0 = (mw & 1) * 4;        // + mt*2 per m-tile

    const bool ptile = (J == I + 64) && diagWarp && thOwn;
    const bool dtile = (I == J) && diagWarp && thOwn;
    const bool doCols = (I != J);

    // ---- epilogue: convert f16x2 -> f32, pos/diag, exp2, row+col sums ----
    float pv = 0.f;
    float rl[2] = {0.f, 0.f}, rh[2] = {0.f, 0.f};
    #pragma unroll
    for (int nt = 0; nt < 8; nt++) {
        float2 v00 = h2f2(cacc[0][nt][0]);   // mt0, row q,   cols 2(lane&3)+{0,1}
        float2 v01 = h2f2(cacc[0][nt][1]);   // mt0, row q+8
        float2 v10 = h2f2(cacc[1][nt][0]);   // mt1, row q
        float2 v11 = h2f2(cacc[1][nt][1]);   // mt1, row q+8

        if (ptile) {   // positive pair values (raw, log2 units)
            if (nt == ntp0)     pv += jsel ? v00.y : v00.x;
            if (nt == ntp0 + 1) pv += jsel ? v01.y : v01.x;
            if (nt == ntp0 + 2) pv += jsel ? v10.y : v10.x;
            if (nt == ntp0 + 3) pv += jsel ? v11.y : v11.x;
        }
        if (dtile) {   // diagonal mask
            if (nt == ntp0)     { if (jsel) v00.y = -1e30f; else v00.x = -1e30f; }
            if (nt == ntp0 + 1) { if (jsel) v01.y = -1e30f; else v01.x = -1e30f; }
            if (nt == ntp0 + 2) { if (jsel) v10.y = -1e30f; else v10.x = -1e30f; }
            if (nt == ntp0 + 3) { if (jsel) v11.y = -1e30f; else v11.x = -1e30f; }
        }

        float e00x = sexp(v00.x), e00y = sexp(v00.y);
        float e01x = sexp(v01.x), e01y = sexp(v01.y);
        float e10x = sexp(v10.x), e10y = sexp(v10.y);
        float e11x = sexp(v11.x), e11y = sexp(v11.y);
        rl[0] += e00x + e00y;  rh[0] += e01x + e01y;
        rl[1] += e10x + e10y;  rh[1] += e11x + e11y;
        if (doCols) {
            float ca = (e00x + e01x) + (e10x + e11x);  // col nt*8+(lane&3)*2
            float cb = (e00y + e01y) + (e10y + e11y);  // col +1
            #pragma unroll
            for (int o = 4; o <= 16; o <<= 1) {
                ca += __shfl_xor_sync(0xffffffffu, ca, o);
                cb += __shfl_xor_sync(0xffffffffu, cb, o);
            }
            if (lane < 4) {
                atomicAdd(&colsum[ch * 64 + nt * 8 + lane * 2], ca);
                atomicAdd(&colsum[ch * 64 + nt * 8 + lane * 2 + 1], cb);
            }
        }
    }

    if (J == I + 64 && diagWarp) {        // flush positives (2x by symmetry)
        #pragma unroll
        for (int o = 16; o >= 1; o >>= 1)
            pv += __shfl_xor_sync(0xffffffffu, pv, o);
        if (lane == 0) atomicAdd(&g_pos, 2.0 * (double)pv);
    }

    // reduce rows across the 4 lanes sharing q, flush to global
    #pragma unroll
    for (int o = 1; o <= 2; o <<= 1) {
        rl[0] += __shfl_xor_sync(0xffffffffu, rl[0], o);
        rh[0] += __shfl_xor_sync(0xffffffffu, rh[0], o);
        rl[1] += __shfl_xor_sync(0xffffffffu, rl[1], o);
        rh[1] += __shfl_xor_sync(0xffffffffu, rh[1], o);
    }
    if ((lane & 3) == 0) {
        #pragma unroll
        for (int mt = 0; mt < 2; mt++) {
            int r = I * 128 + mw * 32 + mt * 16 + q;
            atomicAdd(&g_lrow[r], rl[mt]);
            atomicAdd(&g_lrow[r + 8], rh[mt]);
        }
    }

    __syncthreads();
    if (doCols && tid < 128)
        atomicAdd(&g_lrow[J * 128 + tid], colsum[tid]);
}

// -------------------------------------------------------------------- fin
__global__ void ntxent_fin1() {
    int r = blockIdx.x * 256 + threadIdx.x;
    float v = M0F + log2f(g_lrow[r]);
    #pragma unroll
    for (int o = 16; o >= 1; o >>= 1)
        v += __shfl_xor_sync(0xffffffffu, v, o);
    if ((threadIdx.x & 31) == 0) atomicAdd(&g_acc, (double)v);
}

__global__ void ntxent_fin2(float* out) {
    out[0] = (float)((g_acc - g_pos) * 0.6931471805599453 / (double)NTOT);
}

// ---------------------------------------------------------------------------
extern "C" void kernel_launch(void* const* d_in, const int* in_sizes, int n_in,
                              void* d_out, int out_size) {
    const float* zi = (const float*)d_in[0];
    const float* zj = (const float*)d_in[1];
    float* out = (float*)d_out;

    cudaFuncSetAttribute(ntxent_main,
                         cudaFuncAttributeMaxDynamicSharedMemorySize, 66048);

    ntxent_prep<<<(NTOT * 64) / 256, 256>>>(zi, zj);
    ntxent_main<<<NPAIR, 256, 66048>>>();
    ntxent_fin1<<<NTOT / 256, 256>>>();
    ntxent_fin2<<<1, 1>>>(out);
}

// round 12
// speedup vs baseline: 2.7744x; 1.0829x over previous
#include <cuda_runtime.h>
#include <cuda_fp16.h>
#include <stdint.h>
#include <math.h>

// NT-Xent loss, symmetric-GEMM, fp16 MMA + fp16 accumulators, 2x2 warp grid
// with 64x64 warp tiles (4 warps / 128 threads per CTA): 33% less LDSM
// traffic than 4x2/32x64, HMMA:LDSM = 4:1. One pair-tile (I,J) per CTA;
// exp2(sim'-150) row-sums to block I, col-sums to block J (order-free).

#define NTOT   16384
#define BROWS  8192
#define NPAIR  8256
#define M0F    150.0f

__device__ __align__(128) unsigned char g_Zb[(size_t)NTOT * 256];   // 4 MB fp16
__device__ float  g_lrow[NTOT];
__device__ double g_acc;
__device__ double g_pos;

__device__ __forceinline__ uint32_t smem_u32(const void* p) {
    uint32_t a;
    asm("{ .reg .u64 t; cvta.to.shared.u64 t, %1; cvt.u32.u64 %0, t; }"
        : "=r"(a) : "l"(p));
    return a;
}

// Zero-mean Schraudolph 2^(x-150). Negative bits -> +0 (handles -inf mask).
__device__ __forceinline__ float sexp(float x) {
    int b = __float2int_rn(fmaf(x, 8388608.f, -193420413.f));
    return __int_as_float(max(b, 0));
}

__device__ __forceinline__ float2 h2f2(uint32_t h) {
    __half2 v = *reinterpret_cast<__half2*>(&h);
    return __half22float2(v);
}

// -------------------------------------------------------------------- prep
__global__ void ntxent_prep(const float* __restrict__ zi,
                            const float* __restrict__ zj) {
    int idx = blockIdx.x * blockDim.x + threadIdx.x;
    if (idx < NTOT * 64) {
        int R = idx >> 6, c2 = idx & 63;
        float2 zv = (R < BROWS)
            ? ((const float2*)zi)[(size_t)R * 64 + c2]
            : ((const float2*)zj)[(size_t)(R - BROWS) * 64 + c2];
        const float a = 1.6986436f;    // sqrt(2*log2(e))
        __half2 h = __floats2half2_rn(zv.x * a, zv.y * a);
        uint32_t bits = *reinterpret_cast<uint32_t*>(&h);
        int blk = R >> 7, rl = R & 127;
        int c = c2 * 2, chunk = c >> 3;
        uint32_t byte = (uint32_t)blk * 32768u + (uint32_t)rl * 256u
                      + (uint32_t)(((chunk ^ (rl & 7)) << 4) + (c & 7) * 2);
        *(uint32_t*)(g_Zb + byte) = bits;
    }
    if (idx < NTOT) g_lrow[idx] = 0.f;
    if (idx == 0) { g_acc = 0.0; g_pos = 0.0; }
}

// -------------------------------------------------------------------- main
__global__ void __launch_bounds__(128, 3) ntxent_main() {
    extern __shared__ unsigned char smem[];
    const int tid = threadIdx.x, lane = tid & 31, w = tid >> 5;
    const int mw = w >> 1, ch = w & 1;           // 2x2 warp grid, 64x64 tiles
    const uint32_t sI = smem_u32(smem);          // [0, 32768)
    const uint32_t sJ = sI + 32768;              // [32768, 65536)
    float* colsum = (float*)(smem + 65536);      // 128 floats

    const int b = blockIdx.x;
    const int I = (int)(128.5 - sqrt(128.5 * 128.5 - 2.0 * (double)b));
    const int J = I + (b - (I * 128 - (I * (I - 1)) / 2));

    // ---- load both 32KB blocks (128 threads x 16B x 16 iters each) ----
    #pragma unroll
    for (int i = 0; i < 16; i++)
        asm volatile("cp.async.cg.shared.global [%0], [%1], 16;"
                     :: "r"(sI + tid * 16 + i * 2048),
                        "l"(g_Zb + (size_t)I * 32768 + tid * 16 + i * 2048));
    #pragma unroll
    for (int i = 0; i < 16; i++)
        asm volatile("cp.async.cg.shared.global [%0], [%1], 16;"
                     :: "r"(sJ + tid * 16 + i * 2048),
                        "l"(g_Zb + (size_t)J * 32768 + tid * 16 + i * 2048));
    asm volatile("cp.async.commit_group;");
    colsum[tid] = 0.f;
    asm volatile("cp.async.wait_group 0;");
    __syncthreads();

    // ---- GEMM: f16x2 accumulators cacc[mt 0..3][nt 0..7][2] ----
    uint32_t cacc[4][8][2];
    #pragma unroll
    for (int mt = 0; mt < 4; mt++)
        #pragma unroll
        for (int nt = 0; nt < 8; nt++)
            cacc[mt][nt][0] = cacc[mt][nt][1] = 0u;

    const int rBn = lane & 7, cBk = (lane >> 3) & 1, ntSel = lane >> 4;
    const int rA = mw * 64 + (lane & 15), cbA = lane >> 4;

    #pragma unroll
    for (int kc = 0; kc < 8; kc++) {
        uint32_t af[4][4];
        #pragma unroll
        for (int mt = 0; mt < 4; mt++) {
            int row = rA + mt * 16;
            uint32_t adrA = sI + row * 256 + (((kc * 2 + cbA) ^ (row & 7)) << 4);
            asm volatile("ldmatrix.sync.aligned.m8n8.x4.shared.b16 {%0,%1,%2,%3}, [%4];"
                         : "=r"(af[mt][0]), "=r"(af[mt][1]),
                           "=r"(af[mt][2]), "=r"(af[mt][3]) : "r"(adrA));
        }
        #pragma unroll
        for (int np = 0; np < 4; np++) {
            int row = ch * 64 + (np * 2 + ntSel) * 8 + rBn;
            uint32_t adrB = sJ + row * 256 + (((kc * 2 + cBk) ^ (row & 7)) << 4);
            uint32_t b0, b1, b2, b3;
            asm volatile("ldmatrix.sync.aligned.m8n8.x4.shared.b16 {%0,%1,%2,%3}, [%4];"
                         : "=r"(b0), "=r"(b1), "=r"(b2), "=r"(b3) : "r"(adrB));
            #pragma unroll
            for (int mt = 0; mt < 4; mt++) {
                asm volatile("mma.sync.aligned.m16n8k16.row.col.f16.f16.f16.f16 "
                             "{%0,%1}, {%2,%3,%4,%5}, {%6,%7}, {%0,%1};"
                             : "+r"(cacc[mt][np*2][0]), "+r"(cacc[mt][np*2][1])
                             : "r"(af[mt][0]), "r"(af[mt][1]),
                               "r"(af[mt][2]), "r"(af[mt][3]), "r"(b0), "r"(b1));
                asm volatile("mma.sync.aligned.m16n8k16.row.col.f16.f16.f16.f16 "
                             "{%0,%1}, {%2,%3,%4,%5}, {%6,%7}, {%0,%1};"
                             : "+r"(cacc[mt][np*2+1][0]), "+r"(cacc[mt][np*2+1][1])
                             : "r"(af[mt][0]), "r"(af[mt][1]),
                               "r"(af[mt][2]), "r"(af[mt][3]), "r"(b2), "r"(b3));
            }
        }
    }

    const int q = lane >> 2;              // rows q, q+8 within each m-tile
    // diag/pos live in warps with mw == ch; local col = mt*16 + q (+8):
    // nt = 2mt (row q) / 2mt+1 (row q+8), lane cond (lane&3) == q>>1,
    // element half = q&1.
    const bool diagWarp = (mw == ch);
    const bool thOwn = ((lane & 3) == (q >> 1));
    const int jsel = q & 1;

    // ---- positive pairs (J == I+64): extract BEFORE any masking ----
    if (J == I + 64 && diagWarp) {
        float pv = 0.f;
        if (thOwn) {
            #pragma unroll
            for (int mt = 0; mt < 4; mt++) {
                float2 v0 = h2f2(cacc[mt][2*mt][0]);     // row q
                float2 v1 = h2f2(cacc[mt][2*mt+1][1]);   // row q+8
                pv += (jsel ? v0.y : v0.x) + (jsel ? v1.y : v1.x);
            }
        }
        #pragma unroll
        for (int o = 16; o >= 1; o >>= 1)
            pv += __shfl_xor_sync(0xffffffffu, pv, o);
        if (lane == 0) atomicAdd(&g_pos, 2.0 * (double)pv);
    }
    // ---- diagonal mask on I==J: patch f16 -inf (0xFC00) ----
    if (I == J && diagWarp && thOwn) {
        const uint32_t m = jsel ? 0x0000FFFFu : 0xFFFF0000u;
        const uint32_t s = jsel ? 0xFC000000u : 0x0000FC00u;
        #pragma unroll
        for (int mt = 0; mt < 4; mt++) {
            cacc[mt][2*mt][0]   = (cacc[mt][2*mt][0]   & m) | s;
            cacc[mt][2*mt+1][1] = (cacc[mt][2*mt+1][1] & m) | s;
        }
    }

    // ---- epilogue: exp2(x-150); row sums (regs) + col sums (smem) ----
    const bool doCols = (I != J);
    float rsl[4] = {0.f,0.f,0.f,0.f}, rsh[4] = {0.f,0.f,0.f,0.f};
    #pragma unroll
    for (int nt = 0; nt < 8; nt++) {
        float cax = 0.f, cay = 0.f;
        #pragma unroll
        for (int mt = 0; mt < 4; mt++) {
            float2 v0 = h2f2(cacc[mt][nt][0]);   // row q,  cols 2(lane&3)+{0,1}
            float2 v1 = h2f2(cacc[mt][nt][1]);   // row q+8
            float e0x = sexp(v0.x), e0y = sexp(v0.y);
            float e1x = sexp(v1.x), e1y = sexp(v1.y);
            rsl[mt] += e0x + e0y;
            rsh[mt] += e1x + e1y;
            cax += e0x + e1x;
            cay += e0y + e1y;
        }
        if (doCols) {
            #pragma unroll
            for (int o = 4; o <= 16; o <<= 1) {
                cax += __shfl_xor_sync(0xffffffffu, cax, o);
                cay += __shfl_xor_sync(0xffffffffu, cay, o);
            }
            if (lane < 4) {
                atomicAdd(&colsum[ch * 64 + nt * 8 + lane * 2], cax);
                atomicAdd(&colsum[ch * 64 + nt * 8 + lane * 2 + 1], cay);
            }
        }
    }
    // reduce rows across the 4 lanes sharing q, flush to global
    #pragma unroll
    for (int mt = 0; mt < 4; mt++) {
        #pragma unroll
        for (int o = 1; o <= 2; o <<= 1) {
            rsl[mt] += __shfl_xor_sync(0xffffffffu, rsl[mt], o);
            rsh[mt] += __shfl_xor_sync(0xffffffffu, rsh[mt], o);
        }
    }
    if ((lane & 3) == 0) {
        #pragma unroll
        for (int mt = 0; mt < 4; mt++) {
            int r = I * 128 + mw * 64 + mt * 16 + q;
            atomicAdd(&g_lrow[r], rsl[mt]);
            atomicAdd(&g_lrow[r + 8], rsh[mt]);
        }
    }

    __syncthreads();
    if (doCols)
        atomicAdd(&g_lrow[J * 128 + tid], colsum[tid]);
}

// -------------------------------------------------------------------- fin
__global__ void ntxent_fin1() {
    int r = blockIdx.x * 256 + threadIdx.x;
    float v = M0F + log2f(g_lrow[r]);
    #pragma unroll
    for (int o = 16; o >= 1; o >>= 1)
        v += __shfl_xor_sync(0xffffffffu, v, o);
    if ((threadIdx.x & 31) == 0) atomicAdd(&g_acc, (double)v);
}

__global__ void ntxent_fin2(float* out) {
    out[0] = (float)((g_acc - g_pos) * 0.6931471805599453 / (double)NTOT);
}

// ---------------------------------------------------------------------------
extern "C" void kernel_launch(void* const* d_in, const int* in_sizes, int n_in,
                              void* d_out, int out_size) {
    const float* zi = (const float*)d_in[0];
    const float* zj = (const float*)d_in[1];
    float* out = (float*)d_out;

    cudaFuncSetAttribute(ntxent_main,
                         cudaFuncAttributeMaxDynamicSharedMemorySize, 66048);

    ntxent_prep<<<(NTOT * 64) / 256, 256>>>(zi, zj);
    ntxent_main<<<NPAIR, 128, 66048>>>();
    ntxent_fin1<<<NTOT / 256, 256>>>();
    ntxent_fin2<<<1, 1>>>(out);
}